// round 15
// baseline (speedup 1.0000x reference)
#include <cuda_runtime.h>
#include <cuda_bf16.h>
#include <cfloat>
#include <cstdint>

#define BB 32768
#define AA 16
#define HH 256
#define DD 128
#define KK 2048

// ---------------------------------------------------------------------------
// Globals: plain row-major bf16 weights/codebook (swizzle applied at cp.async)
// ---------------------------------------------------------------------------
__device__ __nv_bfloat16 g_We1b[HH * 64];    // [256][64], k>=16 zero (zero-init)
__device__ __nv_bfloat16 g_We2b[HH * HH];
__device__ __nv_bfloat16 g_We3b[DD * HH];
__device__ __nv_bfloat16 g_Wd1b[HH * DD];
__device__ __nv_bfloat16 g_Wd2b[HH * HH];
__device__ __nv_bfloat16 g_Whb[AA * HH];
__device__ __nv_bfloat16 g_Eb[KK * DD];
__device__ float    g_esq[KK];
__device__ double   g_sums[2];
__device__ unsigned g_ticket;
__device__ unsigned g_bar;

// smem (dynamic, 112KB per CTA -> 2 CTAs/SM, single wave of 256 blocks)
#define B0_OFF 0
#define B1_OFF 32768
#define B2_OFF 65536
#define WB_OFF 98304        // 2 x 8KB W chunks; dist: esq(8K)+red(2K)+bidx
#define SMEM_TOTAL 114688

// ---------------------------------------------------------------------------
__device__ __forceinline__ unsigned su(const void* p) {
    return (unsigned)__cvta_generic_to_shared(p);
}
__device__ __forceinline__ void cp16(unsigned dst, const void* src) {
    asm volatile("cp.async.cg.shared.global [%0], [%1], 16;\n" :: "r"(dst), "l"(src));
}
__device__ __forceinline__ void cpcommit() { asm volatile("cp.async.commit_group;\n"); }
template <int N>
__device__ __forceinline__ void cpwait() { asm volatile("cp.async.wait_group %0;\n" :: "n"(N)); }

__device__ __forceinline__ void ldm4(unsigned addr, unsigned& r0, unsigned& r1,
                                     unsigned& r2, unsigned& r3) {
    asm volatile("ldmatrix.sync.aligned.m8n8.x4.shared.b16 {%0,%1,%2,%3}, [%4];\n"
                 : "=r"(r0), "=r"(r1), "=r"(r2), "=r"(r3) : "r"(addr));
}
__device__ __forceinline__ void mma_bf16(float* c, unsigned a0, unsigned a1, unsigned a2,
                                         unsigned a3, unsigned b0, unsigned b1) {
    asm volatile(
        "mma.sync.aligned.m16n8k16.row.col.f32.bf16.bf16.f32 "
        "{%0,%1,%2,%3}, {%4,%5,%6,%7}, {%8,%9}, {%0,%1,%2,%3};\n"
        : "+f"(c[0]), "+f"(c[1]), "+f"(c[2]), "+f"(c[3])
        : "r"(a0), "r"(a1), "r"(a2), "r"(a3), "r"(b0), "r"(b1));
}
__device__ __forceinline__ unsigned pack_bf16(float a, float b) {
    __nv_bfloat162 h = __floats2bfloat162_rn(a, b);
    return *reinterpret_cast<unsigned*>(&h);
}

__device__ __forceinline__ void block_reduce_add_to(float v, double* target) {
    __shared__ float sbuf[8];
    int lane = threadIdx.x & 31, wid = threadIdx.x >> 5;
#pragma unroll
    for (int o = 16; o; o >>= 1) v += __shfl_xor_sync(0xffffffffu, v, o);
    if (lane == 0) sbuf[wid] = v;
    __syncthreads();
    if (wid == 0) {
        v = (lane < 8) ? sbuf[lane] : 0.0f;
#pragma unroll
        for (int o = 4; o; o >>= 1) v += __shfl_xor_sync(0xffffffffu, v, o);
        if (lane == 0) atomicAdd(target, (double)v);
    }
}

// ---------------------------------------------------------------------------
// W chunk issue: 128 rows x 32 k bf16 (8KB). Conflict-free swizzle:
// chunk c placed at c ^ ((row>>1)&3).
// ---------------------------------------------------------------------------
__device__ __forceinline__ void wissue32(unsigned dstb, const __nv_bfloat16* Wg,
                                         int K, int kc, int tid) {
    int sn = tid >> 1;
    int cb = (tid & 1) * 2;
    const __nv_bfloat16* src = Wg + (size_t)sn * K + kc * 32;
#pragma unroll
    for (int i = 0; i < 2; i++) {
        int c = cb + i;
        cp16(dstb + (sn * 4 + (c ^ ((sn >> 1) & 3))) * 16u, src + c * 8);
    }
    cpcommit();
}

// ---------------------------------------------------------------------------
// GEMM stage (identical to R14)
// ---------------------------------------------------------------------------
template <int K, int AMODE>
__device__ __noinline__ void gemm_stage(
    unsigned Alo, unsigned Ahi,
    const __nv_bfloat16* __restrict__ Wg,
    const float* __restrict__ bias, int n0,
    char* __restrict__ Ob, bool relu, unsigned wb)
{
    constexpr int NCH = K / 32;
    const int tid = threadIdx.x;
    const int w = tid >> 5, L = tid & 31;
    const int wm = w & 3, wn = w >> 2;

    float acc[2][8][4];
#pragma unroll
    for (int a = 0; a < 2; a++)
#pragma unroll
        for (int b = 0; b < 8; b++)
#pragma unroll
            for (int c = 0; c < 4; c++) acc[a][b][c] = 0.0f;

    wissue32(wb, Wg, K, 0, tid);

    for (int kc = 0; kc < NCH; kc++) {
        if (kc + 1 < NCH) {
            wissue32(wb + ((kc + 1) & 1) * 8192u, Wg, K, kc + 1, tid);
            cpwait<1>();
        } else {
            cpwait<0>();
        }
        __syncthreads();

        unsigned Bb = wb + (kc & 1) * 8192u;
#pragma unroll
        for (int ks = 0; ks < 2; ks++) {
            unsigned a[2][4];
#pragma unroll
            for (int mt = 0; mt < 2; mt++) {
                int m  = wm * 32 + mt * 16 + (L & 15);
                int ck = kc * 4 + ks * 2 + (L >> 4);
                unsigned aaddr;
                if (AMODE == 0) {
                    aaddr = Alo + (m * 8 + (ck ^ (m & 7))) * 16u;
                } else if (AMODE == 1) {
                    aaddr = Alo + (m * 16 + ((ck & 8) | ((ck & 7) ^ (m & 7)))) * 16u;
                } else {
                    unsigned base = (ck < 16) ? Alo : Ahi;
                    int c2 = ck & 15;
                    aaddr = base + (m * 16 + ((c2 & 8) | ((c2 & 7) ^ (m & 7)))) * 16u;
                }
                ldm4(aaddr, a[mt][0], a[mt][1], a[mt][2], a[mt][3]);
            }
#pragma unroll
            for (int np = 0; np < 4; np++) {
                int n   = wn * 64 + np * 16 + (L & 7) + ((L >> 4) << 3);
                int ckb = ks * 2 + ((L >> 3) & 1);
                unsigned b0, b1, b2, b3;
                ldm4(Bb + (n * 4 + (ckb ^ ((n >> 1) & 3))) * 16u, b0, b1, b2, b3);
#pragma unroll
                for (int mt = 0; mt < 2; mt++) {
                    mma_bf16(acc[mt][np * 2 + 0], a[mt][0], a[mt][1], a[mt][2], a[mt][3], b0, b1);
                    mma_bf16(acc[mt][np * 2 + 1], a[mt][0], a[mt][1], a[mt][2], a[mt][3], b2, b3);
                }
            }
        }
        __syncthreads();   // also orders all A-reads before epilogue overwrite
    }

    const int g = L >> 2, q2 = (L & 3) * 2;
#pragma unroll
    for (int mt = 0; mt < 2; mt++) {
#pragma unroll
        for (int nt = 0; nt < 8; nt++) {
            int ng = wn * 64 + nt * 8 + q2;
            float b0 = __ldg(&bias[n0 + ng]), b1 = __ldg(&bias[n0 + ng + 1]);
            int c = ng >> 3;
#pragma unroll
            for (int h = 0; h < 2; h++) {
                int m = wm * 32 + mt * 16 + g + 8 * h;
                float v0 = acc[mt][nt][2 * h + 0] + b0;
                float v1 = acc[mt][nt][2 * h + 1] + b1;
                if (relu) { v0 = fmaxf(v0, 0.0f); v1 = fmaxf(v1, 0.0f); }
                int sw = (c & 8) | ((c & 7) ^ (m & 7));
                *reinterpret_cast<unsigned*>(Ob + (m * 16 + sw) * 16 + (ng & 7) * 2)
                    = pack_bf16(v0, v1);
            }
        }
    }
}

// ---------------------------------------------------------------------------
// Megakernel (256 threads, 128 rows/block, 2 CTAs/SM, fused prep + barrier)
// ---------------------------------------------------------------------------
__global__ __launch_bounds__(256, 2)
void mega_kernel(const float* __restrict__ action,
                 const float* __restrict__ We1f, const float* __restrict__ be1,
                 const float* __restrict__ We2f, const float* __restrict__ be2,
                 const float* __restrict__ We3f, const float* __restrict__ be3,
                 const float* __restrict__ E,
                 const float* __restrict__ Wd1f, const float* __restrict__ bd1,
                 const float* __restrict__ Wd2f, const float* __restrict__ bd2,
                 const float* __restrict__ Whf,  const float* __restrict__ bh,
                 float* __restrict__ out) {
    extern __shared__ char sm[];
    const int tid = threadIdx.x;
    const int w = tid >> 5, L = tid & 31;
    const int wm = w & 3, wn = w >> 2;
    const int r0 = blockIdx.x * 128;

    // ---- Phase 0: distributed weight conversion + esq + grid barrier ----
    {
        int base = blockIdx.x * 456;
        for (int i = tid; i < 456; i += 256) {
            int idx = base + i;    // 0..116735 (float4 units)
            const float4* src; uint2* dst; int j, dj;
            if (idx < 16384)       { src = (const float4*)We2f; dst = (uint2*)g_We2b; j = idx;          dj = j; }
            else if (idx < 24576)  { src = (const float4*)We3f; dst = (uint2*)g_We3b; j = idx - 16384;  dj = j; }
            else if (idx < 32768)  { src = (const float4*)Wd1f; dst = (uint2*)g_Wd1b; j = idx - 24576;  dj = j; }
            else if (idx < 49152)  { src = (const float4*)Wd2f; dst = (uint2*)g_Wd2b; j = idx - 32768;  dj = j; }
            else if (idx < 114688) { src = (const float4*)E;    dst = (uint2*)g_Eb;   j = idx - 49152;  dj = j; }
            else if (idx < 115712) { src = (const float4*)We1f; dst = (uint2*)g_We1b; j = idx - 114688;
                                     dj = (j >> 2) * 16 + (j & 3); }
            else                   { src = (const float4*)Whf;  dst = (uint2*)g_Whb;  j = idx - 115712; dj = j; }
            float4 v = src[j];
            uint2 p;
            p.x = pack_bf16(v.x, v.y);
            p.y = pack_bf16(v.z, v.w);
            dst[dj] = p;
        }
        if (blockIdx.x >= 248) {
            int n = (blockIdx.x - 248) * 256 + tid;
            const float4* r = (const float4*)(E + (size_t)n * DD);
            float s = 0.0f;
#pragma unroll
            for (int i = 0; i < DD / 4; i++) {
                float4 v = r[i];
                float a = __bfloat162float(__float2bfloat16_rn(v.x));
                float b = __bfloat162float(__float2bfloat16_rn(v.y));
                float c = __bfloat162float(__float2bfloat16_rn(v.z));
                float d = __bfloat162float(__float2bfloat16_rn(v.w));
                s += a * a + b * b + c * c + d * d;
            }
            g_esq[n] = s;
        }
        if (blockIdx.x == 0 && tid < 2) g_sums[tid] = 0.0;
        __threadfence();
        __syncthreads();
        if (tid == 0) {
            atomicAdd(&g_bar, 1u);
            while (atomicAdd(&g_bar, 0u) < 256u) { __nanosleep(64); }
        }
        __syncthreads();
        __threadfence();
    }

    char* B0p = sm + B0_OFF;
    char* B1p = sm + B1_OFF;
    char* B2p = sm + B2_OFF;
    unsigned b0a = su(B0p), b1a = su(B1p), b2a = su(B2p);
    unsigned wb  = su(sm + WB_OFF);
    float* esq_s = (float*)(sm + WB_OFF);
    float* red_v = (float*)(sm + WB_OFF + 8192);
    int*   red_i = (int*)  (sm + WB_OFF + 9216);
    int*   bidx  = (int*)  (sm + WB_OFF + 10240);

    // ---- Stage 1: pack action into B0 (ACH=8, K padded to 64); h1 -> B1|B2 ----
    {
        char* sActB = B0p;
        {
            int m = tid >> 1, hf = tid & 1;
            const float* ap = action + (size_t)(r0 + m) * AA + hf * 8;
            float4 f0 = __ldg((const float4*)ap);
            float4 f1 = __ldg((const float4*)(ap + 4));
            uint4 pk;
            pk.x = pack_bf16(f0.x, f0.y); pk.y = pack_bf16(f0.z, f0.w);
            pk.z = pack_bf16(f1.x, f1.y); pk.w = pack_bf16(f1.z, f1.w);
            *reinterpret_cast<uint4*>(sActB + (m * 8 + (hf ^ (m & 7))) * 16) = pk;
        }
        uint4 z = make_uint4(0, 0, 0, 0);
#pragma unroll
        for (int t = 0; t < 3; t++) {
            int idx = tid + t * 256;
            int m = idx / 6, c = 2 + idx % 6;
            *reinterpret_cast<uint4*>(sActB + (m * 8 + (c ^ (m & 7))) * 16) = z;
        }
        __syncthreads();
        gemm_stage<64, 0>(b0a, 0, g_We1b,            be1, 0,   B1p, true, wb);
        gemm_stage<64, 0>(b0a, 0, g_We1b + 128 * 64, be1, 128, B2p, true, wb);
    }
    __syncthreads();

    // ---- Stage 2: h2 = relu(h1 @ We2^T + be2): A=(B1,B2) -> out B0 | B1 ----
    gemm_stage<256, 2>(b1a, b2a, g_We2b,             be2, 0,   B0p, true, wb);
    gemm_stage<256, 2>(b1a, b2a, g_We2b + 128 * 256, be2, 128, B1p, true, wb);
    __syncthreads();

    // ---- Stage 3: enc = h2 @ We3^T + be3: A=(B0,B1) -> out B2 ----
    gemm_stage<256, 2>(b0a, b1a, g_We3b, be3, 0, B2p, false, wb);
    __syncthreads();

    // ---- Stage 4: dist + argmin over 2048 codes; enc=B2, E tiles in B0/B1 ----
    {
        unsigned eaddr = b2a;

#pragma unroll
        for (int t = 0; t < 2; t++) {
            int idx = tid + t * 256;
            cp16(su(esq_s) + idx * 16u, g_esq + idx * 4);
        }
#pragma unroll
        for (int t = 0; t < 8; t++) {
            int idx = tid + t * 256;
            int n = idx >> 4, c = idx & 15;
            int sw = (c & 8) | ((c & 7) ^ (n & 7));
            cp16(b0a + (n * 16 + sw) * 16u, (const char*)g_Eb + (size_t)n * 256 + c * 16);
        }
        cpcommit();

        float bestv[4];
        int   besti[4];
#pragma unroll
        for (int i = 0; i < 4; i++) { bestv[i] = FLT_MAX; besti[i] = 0; }

        const float2* esq2 = (const float2*)esq_s;

        for (int t0 = 0; t0 < 16; t0++) {
            if (t0 + 1 < 16) {
                unsigned bb = (t0 & 1) ? b0a : b1a;
                const char* Eg = (const char*)g_Eb + (size_t)(t0 + 1) * 32768;
#pragma unroll
                for (int t = 0; t < 8; t++) {
                    int idx = tid + t * 256;
                    int n = idx >> 4, c = idx & 15;
                    int sw = (c & 8) | ((c & 7) ^ (n & 7));
                    cp16(bb + (n * 16 + sw) * 16u, Eg + (size_t)n * 256 + c * 16);
                }
                cpcommit();
                cpwait<1>();
            } else {
                cpwait<0>();
            }
            __syncthreads();

            unsigned Bb = (t0 & 1) ? b1a : b0a;
            float acc[2][8][4];
#pragma unroll
            for (int a = 0; a < 2; a++)
#pragma unroll
                for (int b = 0; b < 8; b++)
#pragma unroll
                    for (int c = 0; c < 4; c++) acc[a][b][c] = 0.0f;

#pragma unroll
            for (int ks = 0; ks < 8; ks++) {
                unsigned a[2][4];
#pragma unroll
                for (int mt = 0; mt < 2; mt++) {
                    int m  = wm * 32 + mt * 16 + (L & 15);
                    int ck = ks * 2 + (L >> 4);
                    int sw = (ck & 8) | ((ck & 7) ^ (m & 7));
                    ldm4(eaddr + (m * 16 + sw) * 16u, a[mt][0], a[mt][1], a[mt][2], a[mt][3]);
                }
#pragma unroll
                for (int np = 0; np < 4; np++) {
                    int n   = wn * 64 + np * 16 + (L & 7) + ((L >> 4) << 3);
                    int ckb = ks * 2 + ((L >> 3) & 1);
                    int sw  = (ckb & 8) | ((ckb & 7) ^ (n & 7));
                    unsigned b0, b1, b2, b3;
                    ldm4(Bb + (n * 16 + sw) * 16u, b0, b1, b2, b3);
#pragma unroll
                    for (int mt = 0; mt < 2; mt++) {
                        mma_bf16(acc[mt][np * 2 + 0], a[mt][0], a[mt][1], a[mt][2], a[mt][3], b0, b1);
                        mma_bf16(acc[mt][np * 2 + 1], a[mt][0], a[mt][1], a[mt][2], a[mt][3], b2, b3);
                    }
                }
            }

            const int q2 = (L & 3) * 2;
#pragma unroll
            for (int nt = 0; nt < 8; nt++) {
                int n = t0 * 128 + wn * 64 + nt * 8 + q2;
                float2 es = esq2[n >> 1];
#pragma unroll
                for (int mt = 0; mt < 2; mt++) {
#pragma unroll
                    for (int h = 0; h < 2; h++) {
                        int r = mt * 2 + h;
                        float v0 = fmaf(-2.0f, acc[mt][nt][2 * h + 0], es.x);
                        float v1 = fmaf(-2.0f, acc[mt][nt][2 * h + 1], es.y);
                        if (v0 < bestv[r]) { bestv[r] = v0; besti[r] = n; }
                        if (v1 < bestv[r]) { bestv[r] = v1; besti[r] = n + 1; }
                    }
                }
            }
            __syncthreads();
        }

#pragma unroll
        for (int r = 0; r < 4; r++) {
            float v = bestv[r];
            int   ii = besti[r];
#pragma unroll
            for (int o = 1; o <= 2; o <<= 1) {
                float v2 = __shfl_xor_sync(0xffffffffu, v, o);
                int   i2 = __shfl_xor_sync(0xffffffffu, ii, o);
                if (v2 < v || (v2 == v && i2 < ii)) { v = v2; ii = i2; }
            }
            bestv[r] = v; besti[r] = ii;
        }
        if ((L & 3) == 0) {
            int g = L >> 2;
#pragma unroll
            for (int r = 0; r < 4; r++) {
                int mt = r >> 1, h = r & 1;
                int row = wm * 32 + mt * 16 + g + 8 * h;
                red_v[row * 2 + wn] = bestv[r];
                red_i[row * 2 + wn] = besti[r];
            }
        }
        __syncthreads();
        if (tid < 128) {
            float v0 = red_v[tid * 2], v1 = red_v[tid * 2 + 1];
            int   i0 = red_i[tid * 2], i1 = red_i[tid * 2 + 1];
            bidx[tid] = (v1 < v0 || (v1 == v0 && i1 < i0)) ? i1 : i0;
        }
        __syncthreads();
    }

    // ---- Stage 5: gather q = E[idx] -> B0 (swizzled), vq loss (enc in B2) ----
    {
        int m = tid >> 1, hf = tid & 1;
        int code = bidx[m];
        const float4* Ep = reinterpret_cast<const float4*>(E + ((size_t)code << 7) + hf * 64);
        float s = 0.0f;
#pragma unroll
        for (int j = 0; j < 8; j++) {
            int c = hf * 8 + j;
            float4 q0 = __ldg(&Ep[2 * j]);
            float4 q1 = __ldg(&Ep[2 * j + 1]);
            int sw = (c & 8) | ((c & 7) ^ (m & 7));
            uint4 ev = *reinterpret_cast<uint4*>(B2p + (m * 16 + sw) * 16);
            const __nv_bfloat162* eh = reinterpret_cast<const __nv_bfloat162*>(&ev);
            float2 e0 = __bfloat1622float2(eh[0]);
            float2 e1 = __bfloat1622float2(eh[1]);
            float2 e2 = __bfloat1622float2(eh[2]);
            float2 e3 = __bfloat1622float2(eh[3]);
            float d;
            d = e0.x - q0.x; s += d * d;  d = e0.y - q0.y; s += d * d;
            d = e1.x - q0.z; s += d * d;  d = e1.y - q0.w; s += d * d;
            d = e2.x - q1.x; s += d * d;  d = e2.y - q1.y; s += d * d;
            d = e3.x - q1.z; s += d * d;  d = e3.y - q1.w; s += d * d;
            uint4 pk;
            pk.x = pack_bf16(q0.x, q0.y); pk.y = pack_bf16(q0.z, q0.w);
            pk.z = pack_bf16(q1.x, q1.y); pk.w = pack_bf16(q1.z, q1.w);
            *reinterpret_cast<uint4*>(B0p + (m * 16 + sw) * 16) = pk;
        }
        block_reduce_add_to(s, &g_sums[0]);
    }
    __syncthreads();

    // ---- Stage 6: d1 = relu(q @ Wd1^T + bd1): A=B0 -> out B1 | B2 ----
    gemm_stage<128, 1>(b0a, 0, g_Wd1b,             bd1, 0,   B1p, true, wb);
    gemm_stage<128, 1>(b0a, 0, g_Wd1b + 128 * 128, bd1, 128, B2p, true, wb);
    __syncthreads();

    // ---- Stage 7: d2 = relu(d1 @ Wd2^T + bd2): A=(B1,B2) -> out B0 | B1 ----
    gemm_stage<256, 2>(b1a, b2a, g_Wd2b,             bd2, 0,   B0p, true, wb);
    gemm_stage<256, 2>(b1a, b2a, g_Wd2b + 128 * 256, bd2, 128, B1p, true, wb);
    __syncthreads();

    // ---- Stage 8: head = tanh(d2 @ Wh^T + bh), recons loss; A=(B0,B1) ----
    {
        unsigned whaddr = wb;   // 16 x 256 bf16 swizzled (8KB)
#pragma unroll
        for (int i = 0; i < 2; i++) {
            int idx = tid * 2 + i;
            int n = idx >> 5, c = idx & 31;
            int sw = (c & 24) | ((c & 7) ^ (n & 7));
            cp16(whaddr + (n * 32 + sw) * 16u, g_Whb + (size_t)n * HH + c * 8);
        }
        cpcommit(); cpwait<0>();
        __syncthreads();

        float acc[2][4];
#pragma unroll
        for (int a = 0; a < 2; a++)
#pragma unroll
            for (int c = 0; c < 4; c++) acc[a][c] = 0.0f;

#pragma unroll
        for (int ks = 0; ks < 16; ks++) {
            int m  = w * 16 + (L & 15);
            int ck = ks * 2 + (L >> 4);
            unsigned base = (ck < 16) ? b0a : b1a;
            int c2 = ck & 15;
            int sw = (c2 & 8) | ((c2 & 7) ^ (m & 7));
            unsigned a0, a1, a2, a3;
            ldm4(base + (m * 16 + sw) * 16u, a0, a1, a2, a3);
            int n   = (L & 7) + ((L >> 4) << 3);
            int ckb = ks * 2 + ((L >> 3) & 1);
            int swb = (ckb & 24) | ((ckb & 7) ^ (n & 7));
            unsigned b0, b1, b2, b3;
            ldm4(whaddr + (n * 32 + swb) * 16u, b0, b1, b2, b3);
            mma_bf16(acc[0], a0, a1, a2, a3, b0, b1);
            mma_bf16(acc[1], a0, a1, a2, a3, b2, b3);
        }

        const int g = L >> 2, q2 = (L & 3) * 2;
        float s = 0.0f;
#pragma unroll
        for (int nt = 0; nt < 2; nt++) {
            int n = nt * 8 + q2;
            float b0 = __ldg(&bh[n]), b1 = __ldg(&bh[n + 1]);
#pragma unroll
            for (int h = 0; h < 2; h++) {
                int m = w * 16 + g + 8 * h;
                const float* ar = action + (size_t)(r0 + m) * AA + n;
                float t0 = tanhf(acc[nt][2 * h + 0] + b0) - __ldg(&ar[0]);
                float t1 = tanhf(acc[nt][2 * h + 1] + b1) - __ldg(&ar[1]);
                s += t0 * t0 + t1 * t1;
            }
        }
        block_reduce_add_to(s, &g_sums[1]);
    }

    // ---- fused finalize + replay-state reset ----
    if (tid == 0) {
        __threadfence();
        unsigned t = atomicAdd(&g_ticket, 1u);
        if (t == gridDim.x - 1) {
            double vq  = g_sums[0] / ((double)BB * (double)DD);
            double rec = g_sums[1] / ((double)BB * (double)AA);
            out[0] = (float)(rec + 1.25 * vq);
            g_sums[0] = 0.0; g_sums[1] = 0.0;
            g_ticket = 0u;
            g_bar = 0u;
        }
    }
}

// ---------------------------------------------------------------------------
extern "C" void kernel_launch(void* const* d_in, const int* in_sizes, int n_in,
                              void* d_out, int out_size) {
    const float* action = (const float*)d_in[0];
    const float* We1    = (const float*)d_in[1];
    const float* be1    = (const float*)d_in[2];
    const float* We2    = (const float*)d_in[3];
    const float* be2    = (const float*)d_in[4];
    const float* We3    = (const float*)d_in[5];
    const float* be3    = (const float*)d_in[6];
    const float* E      = (const float*)d_in[7];
    const float* Wd1    = (const float*)d_in[8];
    const float* bd1    = (const float*)d_in[9];
    const float* Wd2    = (const float*)d_in[10];
    const float* bd2    = (const float*)d_in[11];
    const float* Wh     = (const float*)d_in[12];
    const float* bh     = (const float*)d_in[13];
    float* out = (float*)d_out;

    cudaFuncSetAttribute((const void*)mega_kernel,
                         cudaFuncAttributeMaxDynamicSharedMemorySize, SMEM_TOTAL);

    mega_kernel<<<BB / 128, 256, SMEM_TOTAL>>>(action, We1, be1, We2, be2,
                                               We3, be3, E, Wd1, bd1,
                                               Wd2, bd2, Wh, bh, out);
}

// round 16
// speedup vs baseline: 1.5639x; 1.5639x over previous
#include <cuda_runtime.h>
#include <cuda_bf16.h>
#include <cfloat>
#include <cstdint>

#define BB 32768
#define AA 16
#define HH 256
#define DD 128
#define KK 2048

// ---------------------------------------------------------------------------
// Globals: plain row-major bf16 weights/codebook (swizzle applied at cp.async)
// ---------------------------------------------------------------------------
__device__ __nv_bfloat16 g_We1b[HH * 64];    // [256][64], k>=16 zero (zero-init)
__device__ __nv_bfloat16 g_We2b[HH * HH];
__device__ __nv_bfloat16 g_We3b[DD * HH];
__device__ __nv_bfloat16 g_Wd1b[HH * DD];
__device__ __nv_bfloat16 g_Wd2b[HH * HH];
__device__ __nv_bfloat16 g_Whb[AA * HH];
__device__ __nv_bfloat16 g_Eb[KK * DD];
__device__ float    g_esq[KK];
__device__ double   g_sums[2];
__device__ unsigned g_ticket;

// smem (dynamic, 112KB per CTA -> 2 CTAs/SM)
#define B0_OFF 0
#define B1_OFF 32768
#define B2_OFF 65536
#define WB_OFF 98304        // 2 x 8KB W chunks; dist: esq(8K)+red(2K)+bidx
#define SMEM_TOTAL 114688

// ---------------------------------------------------------------------------
__device__ __forceinline__ unsigned su(const void* p) {
    return (unsigned)__cvta_generic_to_shared(p);
}
__device__ __forceinline__ void cp16(unsigned dst, const void* src) {
    asm volatile("cp.async.cg.shared.global [%0], [%1], 16;\n" :: "r"(dst), "l"(src));
}
__device__ __forceinline__ void cpcommit() { asm volatile("cp.async.commit_group;\n"); }
template <int N>
__device__ __forceinline__ void cpwait() { asm volatile("cp.async.wait_group %0;\n" :: "n"(N)); }

__device__ __forceinline__ void ldm4(unsigned addr, unsigned& r0, unsigned& r1,
                                     unsigned& r2, unsigned& r3) {
    asm volatile("ldmatrix.sync.aligned.m8n8.x4.shared.b16 {%0,%1,%2,%3}, [%4];\n"
                 : "=r"(r0), "=r"(r1), "=r"(r2), "=r"(r3) : "r"(addr));
}
__device__ __forceinline__ void mma_bf16(float* c, unsigned a0, unsigned a1, unsigned a2,
                                         unsigned a3, unsigned b0, unsigned b1) {
    asm volatile(
        "mma.sync.aligned.m16n8k16.row.col.f32.bf16.bf16.f32 "
        "{%0,%1,%2,%3}, {%4,%5,%6,%7}, {%8,%9}, {%0,%1,%2,%3};\n"
        : "+f"(c[0]), "+f"(c[1]), "+f"(c[2]), "+f"(c[3])
        : "r"(a0), "r"(a1), "r"(a2), "r"(a3), "r"(b0), "r"(b1));
}
__device__ __forceinline__ unsigned pack_bf16(float a, float b) {
    __nv_bfloat162 h = __floats2bfloat162_rn(a, b);
    return *reinterpret_cast<unsigned*>(&h);
}

__device__ __forceinline__ void block_reduce_add_to(float v, double* target) {
    __shared__ float sbuf[8];
    int lane = threadIdx.x & 31, wid = threadIdx.x >> 5;
#pragma unroll
    for (int o = 16; o; o >>= 1) v += __shfl_xor_sync(0xffffffffu, v, o);
    if (lane == 0) sbuf[wid] = v;
    __syncthreads();
    if (wid == 0) {
        v = (lane < 8) ? sbuf[lane] : 0.0f;
#pragma unroll
        for (int o = 4; o; o >>= 1) v += __shfl_xor_sync(0xffffffffu, v, o);
        if (lane == 0) atomicAdd(target, (double)v);
    }
}

// ---------------------------------------------------------------------------
// prep: fp32 -> bf16 (plain layout), We1 padded to K=64, esq, zero sums/ticket
// ---------------------------------------------------------------------------
__global__ void prep_kernel(const float4* __restrict__ We1, const float4* __restrict__ We2,
                            const float4* __restrict__ We3, const float4* __restrict__ Wd1,
                            const float4* __restrict__ Wd2, const float4* __restrict__ Wh,
                            const float4* __restrict__ E, const float* __restrict__ Ef) {
    int blk = blockIdx.x;
    if (blk < 456) {
        int i = blk * 256 + threadIdx.x;
        const float4* src; uint2* dst; int j, dj;
        if (i < 16384)       { src = We2; dst = (uint2*)g_We2b; j = i;          dj = j; }
        else if (i < 24576)  { src = We3; dst = (uint2*)g_We3b; j = i - 16384;  dj = j; }
        else if (i < 32768)  { src = Wd1; dst = (uint2*)g_Wd1b; j = i - 24576;  dj = j; }
        else if (i < 49152)  { src = Wd2; dst = (uint2*)g_Wd2b; j = i - 32768;  dj = j; }
        else if (i < 114688) { src = E;   dst = (uint2*)g_Eb;   j = i - 49152;  dj = j; }
        else if (i < 115712) { src = We1; dst = (uint2*)g_We1b; j = i - 114688;
                               dj = (j >> 2) * 16 + (j & 3); }
        else                 { src = Wh;  dst = (uint2*)g_Whb;  j = i - 115712; dj = j; }
        float4 v = src[j];
        uint2 p;
        p.x = pack_bf16(v.x, v.y);
        p.y = pack_bf16(v.z, v.w);
        dst[dj] = p;
    } else {
        if (blk == 456 && threadIdx.x < 2) g_sums[threadIdx.x] = 0.0;
        if (blk == 456 && threadIdx.x == 2) g_ticket = 0u;
        int n = (blk - 456) * 256 + threadIdx.x;
        const float4* r = (const float4*)(Ef + (size_t)n * DD);
        float s = 0.0f;
#pragma unroll
        for (int i = 0; i < DD / 4; i++) {
            float4 v = r[i];
            float a = __bfloat162float(__float2bfloat16_rn(v.x));
            float b = __bfloat162float(__float2bfloat16_rn(v.y));
            float c = __bfloat162float(__float2bfloat16_rn(v.z));
            float d = __bfloat162float(__float2bfloat16_rn(v.w));
            s += a * a + b * b + c * c + d * d;
        }
        g_esq[n] = s;
    }
}

// ---------------------------------------------------------------------------
// W chunk issue: 128 rows x 32 k bf16 (8KB). Conflict-free swizzle:
// chunk c placed at c ^ ((row>>1)&3).
// ---------------------------------------------------------------------------
__device__ __forceinline__ void wissue32(unsigned dstb, const __nv_bfloat16* Wg,
                                         int K, int kc, int tid) {
    int sn = tid >> 1;
    int cb = (tid & 1) * 2;
    const __nv_bfloat16* src = Wg + (size_t)sn * K + kc * 32;
#pragma unroll
    for (int i = 0; i < 2; i++) {
        int c = cb + i;
        cp16(dstb + (sn * 4 + (c ^ ((sn >> 1) & 3))) * 16u, src + c * 8);
    }
    cpcommit();
}

// ---------------------------------------------------------------------------
// GEMM stage (256 threads, M=128, BN=128): C = act(A[128xK] @ W[128xK]^T + b)
// A modes: 0 = single region ACH=8; 1 = single bank ACH=16; 2 = k-split banks.
// ---------------------------------------------------------------------------
template <int K, int AMODE>
__device__ __noinline__ void gemm_stage(
    unsigned Alo, unsigned Ahi,
    const __nv_bfloat16* __restrict__ Wg,
    const float* __restrict__ bias, int n0,
    char* __restrict__ Ob, bool relu, unsigned wb)
{
    constexpr int NCH = K / 32;
    const int tid = threadIdx.x;
    const int w = tid >> 5, L = tid & 31;
    const int wm = w & 3, wn = w >> 2;

    float acc[2][8][4];
#pragma unroll
    for (int a = 0; a < 2; a++)
#pragma unroll
        for (int b = 0; b < 8; b++)
#pragma unroll
            for (int c = 0; c < 4; c++) acc[a][b][c] = 0.0f;

    wissue32(wb, Wg, K, 0, tid);

    for (int kc = 0; kc < NCH; kc++) {
        if (kc + 1 < NCH) {
            wissue32(wb + ((kc + 1) & 1) * 8192u, Wg, K, kc + 1, tid);
            cpwait<1>();
        } else {
            cpwait<0>();
        }
        __syncthreads();

        unsigned Bb = wb + (kc & 1) * 8192u;
#pragma unroll
        for (int ks = 0; ks < 2; ks++) {
            unsigned a[2][4];
#pragma unroll
            for (int mt = 0; mt < 2; mt++) {
                int m  = wm * 32 + mt * 16 + (L & 15);
                int ck = kc * 4 + ks * 2 + (L >> 4);
                unsigned aaddr;
                if (AMODE == 0) {
                    aaddr = Alo + (m * 8 + (ck ^ (m & 7))) * 16u;
                } else if (AMODE == 1) {
                    aaddr = Alo + (m * 16 + ((ck & 8) | ((ck & 7) ^ (m & 7)))) * 16u;
                } else {
                    unsigned base = (ck < 16) ? Alo : Ahi;
                    int c2 = ck & 15;
                    aaddr = base + (m * 16 + ((c2 & 8) | ((c2 & 7) ^ (m & 7)))) * 16u;
                }
                ldm4(aaddr, a[mt][0], a[mt][1], a[mt][2], a[mt][3]);
            }
#pragma unroll
            for (int np = 0; np < 4; np++) {
                int n   = wn * 64 + np * 16 + (L & 7) + ((L >> 4) << 3);
                int ckb = ks * 2 + ((L >> 3) & 1);
                unsigned b0, b1, b2, b3;
                ldm4(Bb + (n * 4 + (ckb ^ ((n >> 1) & 3))) * 16u, b0, b1, b2, b3);
#pragma unroll
                for (int mt = 0; mt < 2; mt++) {
                    mma_bf16(acc[mt][np * 2 + 0], a[mt][0], a[mt][1], a[mt][2], a[mt][3], b0, b1);
                    mma_bf16(acc[mt][np * 2 + 1], a[mt][0], a[mt][1], a[mt][2], a[mt][3], b2, b3);
                }
            }
        }
        __syncthreads();   // also orders all A-reads before epilogue overwrite
    }

    const int g = L >> 2, q2 = (L & 3) * 2;
#pragma unroll
    for (int mt = 0; mt < 2; mt++) {
#pragma unroll
        for (int nt = 0; nt < 8; nt++) {
            int ng = wn * 64 + nt * 8 + q2;
            float b0 = __ldg(&bias[n0 + ng]), b1 = __ldg(&bias[n0 + ng + 1]);
            int c = ng >> 3;
#pragma unroll
            for (int h = 0; h < 2; h++) {
                int m = wm * 32 + mt * 16 + g + 8 * h;
                float v0 = acc[mt][nt][2 * h + 0] + b0;
                float v1 = acc[mt][nt][2 * h + 1] + b1;
                if (relu) { v0 = fmaxf(v0, 0.0f); v1 = fmaxf(v1, 0.0f); }
                int sw = (c & 8) | ((c & 7) ^ (m & 7));
                *reinterpret_cast<unsigned*>(Ob + (m * 16 + sw) * 16 + (ng & 7) * 2)
                    = pack_bf16(v0, v1);
            }
        }
    }
}

// ---------------------------------------------------------------------------
// Megakernel (256 threads, 128 rows/block, 2 CTAs/SM)
// ---------------------------------------------------------------------------
__global__ __launch_bounds__(256, 2)
void mega_kernel(const float* __restrict__ action,
                 const float* __restrict__ be1, const float* __restrict__ be2,
                 const float* __restrict__ be3, const float* __restrict__ E,
                 const float* __restrict__ bd1, const float* __restrict__ bd2,
                 const float* __restrict__ bh, float* __restrict__ out) {
    extern __shared__ char sm[];
    const int tid = threadIdx.x;
    const int w = tid >> 5, L = tid & 31;
    const int wm = w & 3, wn = w >> 2;
    const int r0 = blockIdx.x * 128;

    char* B0p = sm + B0_OFF;
    char* B1p = sm + B1_OFF;
    char* B2p = sm + B2_OFF;
    unsigned b0a = su(B0p), b1a = su(B1p), b2a = su(B2p);
    unsigned wb  = su(sm + WB_OFF);
    float* esq_s = (float*)(sm + WB_OFF);
    float* red_v = (float*)(sm + WB_OFF + 8192);
    int*   red_i = (int*)  (sm + WB_OFF + 9216);
    int*   bidx  = (int*)  (sm + WB_OFF + 10240);

    // ---- Stage 1: pack action into B0 (ACH=8, K padded to 64); h1 -> B1|B2 ----
    {
        char* sActB = B0p;
        {
            int m = tid >> 1, hf = tid & 1;
            const float* ap = action + (size_t)(r0 + m) * AA + hf * 8;
            float4 f0 = __ldg((const float4*)ap);
            float4 f1 = __ldg((const float4*)(ap + 4));
            uint4 pk;
            pk.x = pack_bf16(f0.x, f0.y); pk.y = pack_bf16(f0.z, f0.w);
            pk.z = pack_bf16(f1.x, f1.y); pk.w = pack_bf16(f1.z, f1.w);
            *reinterpret_cast<uint4*>(sActB + (m * 8 + (hf ^ (m & 7))) * 16) = pk;
        }
        uint4 z = make_uint4(0, 0, 0, 0);
#pragma unroll
        for (int t = 0; t < 3; t++) {
            int idx = tid + t * 256;
            int m = idx / 6, c = 2 + idx % 6;
            *reinterpret_cast<uint4*>(sActB + (m * 8 + (c ^ (m & 7))) * 16) = z;
        }
        __syncthreads();
        gemm_stage<64, 0>(b0a, 0, g_We1b,            be1, 0,   B1p, true, wb);
        gemm_stage<64, 0>(b0a, 0, g_We1b + 128 * 64, be1, 128, B2p, true, wb);
    }
    __syncthreads();

    // ---- Stage 2: h2 = relu(h1 @ We2^T + be2): A=(B1,B2) -> out B0 | B1 ----
    gemm_stage<256, 2>(b1a, b2a, g_We2b,             be2, 0,   B0p, true, wb);
    gemm_stage<256, 2>(b1a, b2a, g_We2b + 128 * 256, be2, 128, B1p, true, wb);
    __syncthreads();

    // ---- Stage 3: enc = h2 @ We3^T + be3: A=(B0,B1) -> out B2 ----
    gemm_stage<256, 2>(b0a, b1a, g_We3b, be3, 0, B2p, false, wb);
    __syncthreads();

    // ---- Stage 4: dist + argmin over 2048 codes; enc=B2, E tiles in B0/B1 ----
    {
        unsigned eaddr = b2a;

#pragma unroll
        for (int t = 0; t < 2; t++) {
            int idx = tid + t * 256;
            cp16(su(esq_s) + idx * 16u, g_esq + idx * 4);
        }
#pragma unroll
        for (int t = 0; t < 8; t++) {
            int idx = tid + t * 256;
            int n = idx >> 4, c = idx & 15;
            int sw = (c & 8) | ((c & 7) ^ (n & 7));
            cp16(b0a + (n * 16 + sw) * 16u, (const char*)g_Eb + (size_t)n * 256 + c * 16);
        }
        cpcommit();

        float bestv[4];
        int   besti[4];
#pragma unroll
        for (int i = 0; i < 4; i++) { bestv[i] = FLT_MAX; besti[i] = 0; }

        const float2* esq2 = (const float2*)esq_s;

        for (int t0 = 0; t0 < 16; t0++) {
            if (t0 + 1 < 16) {
                unsigned bb = (t0 & 1) ? b0a : b1a;
                const char* Eg = (const char*)g_Eb + (size_t)(t0 + 1) * 32768;
#pragma unroll
                for (int t = 0; t < 8; t++) {
                    int idx = tid + t * 256;
                    int n = idx >> 4, c = idx & 15;
                    int sw = (c & 8) | ((c & 7) ^ (n & 7));
                    cp16(bb + (n * 16 + sw) * 16u, Eg + (size_t)n * 256 + c * 16);
                }
                cpcommit();
                cpwait<1>();
            } else {
                cpwait<0>();
            }
            __syncthreads();

            unsigned Bb = (t0 & 1) ? b1a : b0a;
            float acc[2][8][4];
#pragma unroll
            for (int a = 0; a < 2; a++)
#pragma unroll
                for (int b = 0; b < 8; b++)
#pragma unroll
                    for (int c = 0; c < 4; c++) acc[a][b][c] = 0.0f;

#pragma unroll
            for (int ks = 0; ks < 8; ks++) {
                unsigned a[2][4];
#pragma unroll
                for (int mt = 0; mt < 2; mt++) {
                    int m  = wm * 32 + mt * 16 + (L & 15);
                    int ck = ks * 2 + (L >> 4);
                    int sw = (ck & 8) | ((ck & 7) ^ (m & 7));
                    ldm4(eaddr + (m * 16 + sw) * 16u, a[mt][0], a[mt][1], a[mt][2], a[mt][3]);
                }
#pragma unroll
                for (int np = 0; np < 4; np++) {
                    int n   = wn * 64 + np * 16 + (L & 7) + ((L >> 4) << 3);
                    int ckb = ks * 2 + ((L >> 3) & 1);
                    int sw  = (ckb & 8) | ((ckb & 7) ^ (n & 7));
                    unsigned b0, b1, b2, b3;
                    ldm4(Bb + (n * 16 + sw) * 16u, b0, b1, b2, b3);
#pragma unroll
                    for (int mt = 0; mt < 2; mt++) {
                        mma_bf16(acc[mt][np * 2 + 0], a[mt][0], a[mt][1], a[mt][2], a[mt][3], b0, b1);
                        mma_bf16(acc[mt][np * 2 + 1], a[mt][0], a[mt][1], a[mt][2], a[mt][3], b2, b3);
                    }
                }
            }

            const int q2 = (L & 3) * 2;
#pragma unroll
            for (int nt = 0; nt < 8; nt++) {
                int n = t0 * 128 + wn * 64 + nt * 8 + q2;
                float2 es = esq2[n >> 1];
#pragma unroll
                for (int mt = 0; mt < 2; mt++) {
#pragma unroll
                    for (int h = 0; h < 2; h++) {
                        int r = mt * 2 + h;
                        float v0 = fmaf(-2.0f, acc[mt][nt][2 * h + 0], es.x);
                        float v1 = fmaf(-2.0f, acc[mt][nt][2 * h + 1], es.y);
                        if (v0 < bestv[r]) { bestv[r] = v0; besti[r] = n; }
                        if (v1 < bestv[r]) { bestv[r] = v1; besti[r] = n + 1; }
                    }
                }
            }
            __syncthreads();
        }

#pragma unroll
        for (int r = 0; r < 4; r++) {
            float v = bestv[r];
            int   ii = besti[r];
#pragma unroll
            for (int o = 1; o <= 2; o <<= 1) {
                float v2 = __shfl_xor_sync(0xffffffffu, v, o);
                int   i2 = __shfl_xor_sync(0xffffffffu, ii, o);
                if (v2 < v || (v2 == v && i2 < ii)) { v = v2; ii = i2; }
            }
            bestv[r] = v; besti[r] = ii;
        }
        if ((L & 3) == 0) {
            int g = L >> 2;
#pragma unroll
            for (int r = 0; r < 4; r++) {
                int mt = r >> 1, h = r & 1;
                int row = wm * 32 + mt * 16 + g + 8 * h;
                red_v[row * 2 + wn] = bestv[r];
                red_i[row * 2 + wn] = besti[r];
            }
        }
        __syncthreads();
        if (tid < 128) {
            float v0 = red_v[tid * 2], v1 = red_v[tid * 2 + 1];
            int   i0 = red_i[tid * 2], i1 = red_i[tid * 2 + 1];
            bidx[tid] = (v1 < v0 || (v1 == v0 && i1 < i0)) ? i1 : i0;
        }
        __syncthreads();
    }

    // ---- Stage 5: gather q = E[idx] -> B0 (swizzled), vq loss (enc in B2) ----
    {
        int m = tid >> 1, hf = tid & 1;
        int code = bidx[m];
        const float4* Ep = reinterpret_cast<const float4*>(E + ((size_t)code << 7) + hf * 64);
        float s = 0.0f;
#pragma unroll
        for (int j = 0; j < 8; j++) {
            int c = hf * 8 + j;
            float4 q0 = __ldg(&Ep[2 * j]);
            float4 q1 = __ldg(&Ep[2 * j + 1]);
            int sw = (c & 8) | ((c & 7) ^ (m & 7));
            uint4 ev = *reinterpret_cast<uint4*>(B2p + (m * 16 + sw) * 16);
            const __nv_bfloat162* eh = reinterpret_cast<const __nv_bfloat162*>(&ev);
            float2 e0 = __bfloat1622float2(eh[0]);
            float2 e1 = __bfloat1622float2(eh[1]);
            float2 e2 = __bfloat1622float2(eh[2]);
            float2 e3 = __bfloat1622float2(eh[3]);
            float d;
            d = e0.x - q0.x; s += d * d;  d = e0.y - q0.y; s += d * d;
            d = e1.x - q0.z; s += d * d;  d = e1.y - q0.w; s += d * d;
            d = e2.x - q1.x; s += d * d;  d = e2.y - q1.y; s += d * d;
            d = e3.x - q1.z; s += d * d;  d = e3.y - q1.w; s += d * d;
            uint4 pk;
            pk.x = pack_bf16(q0.x, q0.y); pk.y = pack_bf16(q0.z, q0.w);
            pk.z = pack_bf16(q1.x, q1.y); pk.w = pack_bf16(q1.z, q1.w);
            *reinterpret_cast<uint4*>(B0p + (m * 16 + sw) * 16) = pk;
        }
        block_reduce_add_to(s, &g_sums[0]);
    }
    __syncthreads();

    // ---- Stage 6: d1 = relu(q @ Wd1^T + bd1): A=B0 -> out B1 | B2 ----
    gemm_stage<128, 1>(b0a, 0, g_Wd1b,             bd1, 0,   B1p, true, wb);
    gemm_stage<128, 1>(b0a, 0, g_Wd1b + 128 * 128, bd1, 128, B2p, true, wb);
    __syncthreads();

    // ---- Stage 7: d2 = relu(d1 @ Wd2^T + bd2): A=(B1,B2) -> out B0 | B1 ----
    gemm_stage<256, 2>(b1a, b2a, g_Wd2b,             bd2, 0,   B0p, true, wb);
    gemm_stage<256, 2>(b1a, b2a, g_Wd2b + 128 * 256, bd2, 128, B1p, true, wb);
    __syncthreads();

    // ---- Stage 8: head = tanh(d2 @ Wh^T + bh), recons loss; A=(B0,B1) ----
    {
        unsigned whaddr = wb;   // 16 x 256 bf16 swizzled (8KB)
#pragma unroll
        for (int i = 0; i < 2; i++) {
            int idx = tid * 2 + i;
            int n = idx >> 5, c = idx & 31;
            int sw = (c & 24) | ((c & 7) ^ (n & 7));
            cp16(whaddr + (n * 32 + sw) * 16u, g_Whb + (size_t)n * HH + c * 8);
        }
        cpcommit(); cpwait<0>();
        __syncthreads();

        float acc[2][4];
#pragma unroll
        for (int a = 0; a < 2; a++)
#pragma unroll
            for (int c = 0; c < 4; c++) acc[a][c] = 0.0f;

#pragma unroll
        for (int ks = 0; ks < 16; ks++) {
            int m  = w * 16 + (L & 15);
            int ck = ks * 2 + (L >> 4);
            unsigned base = (ck < 16) ? b0a : b1a;
            int c2 = ck & 15;
            int sw = (c2 & 8) | ((c2 & 7) ^ (m & 7));
            unsigned a0, a1, a2, a3;
            ldm4(base + (m * 16 + sw) * 16u, a0, a1, a2, a3);
            int n   = (L & 7) + ((L >> 4) << 3);
            int ckb = ks * 2 + ((L >> 3) & 1);
            int swb = (ckb & 24) | ((ckb & 7) ^ (n & 7));
            unsigned b0, b1, b2, b3;
            ldm4(whaddr + (n * 32 + swb) * 16u, b0, b1, b2, b3);
            mma_bf16(acc[0], a0, a1, a2, a3, b0, b1);
            mma_bf16(acc[1], a0, a1, a2, a3, b2, b3);
        }

        const int g = L >> 2, q2 = (L & 3) * 2;
        float s = 0.0f;
#pragma unroll
        for (int nt = 0; nt < 2; nt++) {
            int n = nt * 8 + q2;
            float b0 = __ldg(&bh[n]), b1 = __ldg(&bh[n + 1]);
#pragma unroll
            for (int h = 0; h < 2; h++) {
                int m = w * 16 + g + 8 * h;
                const float* ar = action + (size_t)(r0 + m) * AA + n;
                float t0 = tanhf(acc[nt][2 * h + 0] + b0) - __ldg(&ar[0]);
                float t1 = tanhf(acc[nt][2 * h + 1] + b1) - __ldg(&ar[1]);
                s += t0 * t0 + t1 * t1;
            }
        }
        block_reduce_add_to(s, &g_sums[1]);
    }

    // ---- fused finalize ----
    if (tid == 0) {
        __threadfence();
        unsigned t = atomicAdd(&g_ticket, 1u);
        if (t == gridDim.x - 1) {
            double vq  = g_sums[0] / ((double)BB * (double)DD);
            double rec = g_sums[1] / ((double)BB * (double)AA);
            out[0] = (float)(rec + 1.25 * vq);
        }
    }
}

// ---------------------------------------------------------------------------
extern "C" void kernel_launch(void* const* d_in, const int* in_sizes, int n_in,
                              void* d_out, int out_size) {
    const float* action = (const float*)d_in[0];
    const float* We1    = (const float*)d_in[1];
    const float* be1    = (const float*)d_in[2];
    const float* We2    = (const float*)d_in[3];
    const float* be2    = (const float*)d_in[4];
    const float* We3    = (const float*)d_in[5];
    const float* be3    = (const float*)d_in[6];
    const float* E      = (const float*)d_in[7];
    const float* Wd1    = (const float*)d_in[8];
    const float* bd1    = (const float*)d_in[9];
    const float* Wd2    = (const float*)d_in[10];
    const float* bd2    = (const float*)d_in[11];
    const float* Wh     = (const float*)d_in[12];
    const float* bh     = (const float*)d_in[13];
    float* out = (float*)d_out;

    cudaFuncSetAttribute((const void*)mega_kernel,
                         cudaFuncAttributeMaxDynamicSharedMemorySize, SMEM_TOTAL);

    prep_kernel<<<464, 256>>>((const float4*)We1, (const float4*)We2,
                              (const float4*)We3, (const float4*)Wd1,
                              (const float4*)Wd2, (const float4*)Wh,
                              (const float4*)E, E);
    mega_kernel<<<BB / 128, 256, SMEM_TOTAL>>>(action, be1, be2, be3, E,
                                               bd1, bd2, bh, out);
}

// round 17
// speedup vs baseline: 1.5643x; 1.0003x over previous
#include <cuda_runtime.h>
#include <cuda_bf16.h>
#include <cfloat>
#include <cstdint>

#define BB 32768
#define AA 16
#define HH 256
#define DD 128
#define KK 2048

// ---------------------------------------------------------------------------
// Globals: plain row-major bf16 weights/codebook (swizzle applied at cp.async)
// ---------------------------------------------------------------------------
__device__ __nv_bfloat16 g_We1b[HH * 64];    // [256][64], k>=16 zero (zero-init)
__device__ __nv_bfloat16 g_We2b[HH * HH];
__device__ __nv_bfloat16 g_We3b[DD * HH];
__device__ __nv_bfloat16 g_Wd1b[HH * DD];
__device__ __nv_bfloat16 g_Wd2b[HH * HH];
__device__ __nv_bfloat16 g_Whb[AA * HH];
__device__ __nv_bfloat16 g_Eb[KK * DD];
__device__ float    g_esq[KK];
__device__ double   g_sums[2];
__device__ unsigned g_ticket;

// smem (dynamic, 112KB per CTA -> 2 CTAs/SM)
#define B0_OFF 0
#define B1_OFF 32768
#define B2_OFF 65536
#define WB_OFF 98304        // 2 x 8KB W chunks; dist: esq(8K)+red(2K)+bidx
#define SMEM_TOTAL 114688

// ---------------------------------------------------------------------------
__device__ __forceinline__ unsigned su(const void* p) {
    return (unsigned)__cvta_generic_to_shared(p);
}
__device__ __forceinline__ void cp16(unsigned dst, const void* src) {
    asm volatile("cp.async.cg.shared.global [%0], [%1], 16;\n" :: "r"(dst), "l"(src));
}
__device__ __forceinline__ void cpcommit() { asm volatile("cp.async.commit_group;\n"); }
template <int N>
__device__ __forceinline__ void cpwait() { asm volatile("cp.async.wait_group %0;\n" :: "n"(N)); }

__device__ __forceinline__ void ldm4(unsigned addr, unsigned& r0, unsigned& r1,
                                     unsigned& r2, unsigned& r3) {
    asm volatile("ldmatrix.sync.aligned.m8n8.x4.shared.b16 {%0,%1,%2,%3}, [%4];\n"
                 : "=r"(r0), "=r"(r1), "=r"(r2), "=r"(r3) : "r"(addr));
}
__device__ __forceinline__ void mma_bf16(float* c, unsigned a0, unsigned a1, unsigned a2,
                                         unsigned a3, unsigned b0, unsigned b1) {
    asm volatile(
        "mma.sync.aligned.m16n8k16.row.col.f32.bf16.bf16.f32 "
        "{%0,%1,%2,%3}, {%4,%5,%6,%7}, {%8,%9}, {%0,%1,%2,%3};\n"
        : "+f"(c[0]), "+f"(c[1]), "+f"(c[2]), "+f"(c[3])
        : "r"(a0), "r"(a1), "r"(a2), "r"(a3), "r"(b0), "r"(b1));
}
__device__ __forceinline__ unsigned pack_bf16(float a, float b) {
    __nv_bfloat162 h = __floats2bfloat162_rn(a, b);
    return *reinterpret_cast<unsigned*>(&h);
}

__device__ __forceinline__ void block_reduce_add_to(float v, double* target) {
    __shared__ float sbuf[8];
    int lane = threadIdx.x & 31, wid = threadIdx.x >> 5;
#pragma unroll
    for (int o = 16; o; o >>= 1) v += __shfl_xor_sync(0xffffffffu, v, o);
    if (lane == 0) sbuf[wid] = v;
    __syncthreads();
    if (wid == 0) {
        v = (lane < 8) ? sbuf[lane] : 0.0f;
#pragma unroll
        for (int o = 4; o; o >>= 1) v += __shfl_xor_sync(0xffffffffu, v, o);
        if (lane == 0) atomicAdd(target, (double)v);
    }
}

// ---------------------------------------------------------------------------
// prep: fp32 -> bf16 (plain layout), We1 padded to K=64, esq, zero sums/ticket
// ---------------------------------------------------------------------------
__global__ void prep_kernel(const float4* __restrict__ We1, const float4* __restrict__ We2,
                            const float4* __restrict__ We3, const float4* __restrict__ Wd1,
                            const float4* __restrict__ Wd2, const float4* __restrict__ Wh,
                            const float4* __restrict__ E, const float* __restrict__ Ef) {
    int blk = blockIdx.x;
    if (blk < 456) {
        int i = blk * 256 + threadIdx.x;
        const float4* src; uint2* dst; int j, dj;
        if (i < 16384)       { src = We2; dst = (uint2*)g_We2b; j = i;          dj = j; }
        else if (i < 24576)  { src = We3; dst = (uint2*)g_We3b; j = i - 16384;  dj = j; }
        else if (i < 32768)  { src = Wd1; dst = (uint2*)g_Wd1b; j = i - 24576;  dj = j; }
        else if (i < 49152)  { src = Wd2; dst = (uint2*)g_Wd2b; j = i - 32768;  dj = j; }
        else if (i < 114688) { src = E;   dst = (uint2*)g_Eb;   j = i - 49152;  dj = j; }
        else if (i < 115712) { src = We1; dst = (uint2*)g_We1b; j = i - 114688;
                               dj = (j >> 2) * 16 + (j & 3); }
        else                 { src = Wh;  dst = (uint2*)g_Whb;  j = i - 115712; dj = j; }
        float4 v = src[j];
        uint2 p;
        p.x = pack_bf16(v.x, v.y);
        p.y = pack_bf16(v.z, v.w);
        dst[dj] = p;
    } else {
        if (blk == 456 && threadIdx.x < 2) g_sums[threadIdx.x] = 0.0;
        if (blk == 456 && threadIdx.x == 2) g_ticket = 0u;
        int n = (blk - 456) * 256 + threadIdx.x;
        const float4* r = (const float4*)(Ef + (size_t)n * DD);
        float s = 0.0f;
#pragma unroll
        for (int i = 0; i < DD / 4; i++) {
            float4 v = r[i];
            float a = __bfloat162float(__float2bfloat16_rn(v.x));
            float b = __bfloat162float(__float2bfloat16_rn(v.y));
            float c = __bfloat162float(__float2bfloat16_rn(v.z));
            float d = __bfloat162float(__float2bfloat16_rn(v.w));
            s += a * a + b * b + c * c + d * d;
        }
        g_esq[n] = s;
    }
}

// ---------------------------------------------------------------------------
// W chunk issue: 128 rows x 32 k bf16 (8KB). Conflict-free swizzle:
// chunk c placed at c ^ ((row>>1)&3).
// ---------------------------------------------------------------------------
__device__ __forceinline__ void wissue32(unsigned dstb, const __nv_bfloat16* Wg,
                                         int K, int kc, int tid) {
    int sn = tid >> 1;
    int cb = (tid & 1) * 2;
    const __nv_bfloat16* src = Wg + (size_t)sn * K + kc * 32;
#pragma unroll
    for (int i = 0; i < 2; i++) {
        int c = cb + i;
        cp16(dstb + (sn * 4 + (c ^ ((sn >> 1) & 3))) * 16u, src + c * 8);
    }
    cpcommit();
}

// ---------------------------------------------------------------------------
// GEMM stage (256 threads, M=128, BN=128): C = act(A[128xK] @ W[128xK]^T + b)
// A modes: 0 = single region ACH=8; 1 = single bank ACH=16; 2 = k-split banks.
// TRAIL: emit the final chunk's trailing __syncthreads (needed only when the
// epilogue or the immediately following code writes a bank that this stage's
// lagging warps may still be reading).
// ---------------------------------------------------------------------------
template <int K, int AMODE, bool TRAIL>
__device__ __noinline__ void gemm_stage(
    unsigned Alo, unsigned Ahi,
    const __nv_bfloat16* __restrict__ Wg,
    const float* __restrict__ bias, int n0,
    char* __restrict__ Ob, bool relu, unsigned wb)
{
    constexpr int NCH = K / 32;
    const int tid = threadIdx.x;
    const int w = tid >> 5, L = tid & 31;
    const int wm = w & 3, wn = w >> 2;

    float acc[2][8][4];
#pragma unroll
    for (int a = 0; a < 2; a++)
#pragma unroll
        for (int b = 0; b < 8; b++)
#pragma unroll
            for (int c = 0; c < 4; c++) acc[a][b][c] = 0.0f;

    wissue32(wb, Wg, K, 0, tid);

    for (int kc = 0; kc < NCH; kc++) {
        if (kc + 1 < NCH) {
            wissue32(wb + ((kc + 1) & 1) * 8192u, Wg, K, kc + 1, tid);
            cpwait<1>();
        } else {
            cpwait<0>();
        }
        __syncthreads();

        unsigned Bb = wb + (kc & 1) * 8192u;
#pragma unroll
        for (int ks = 0; ks < 2; ks++) {
            unsigned a[2][4];
#pragma unroll
            for (int mt = 0; mt < 2; mt++) {
                int m  = wm * 32 + mt * 16 + (L & 15);
                int ck = kc * 4 + ks * 2 + (L >> 4);
                unsigned aaddr;
                if (AMODE == 0) {
                    aaddr = Alo + (m * 8 + (ck ^ (m & 7))) * 16u;
                } else if (AMODE == 1) {
                    aaddr = Alo + (m * 16 + ((ck & 8) | ((ck & 7) ^ (m & 7)))) * 16u;
                } else {
                    unsigned base = (ck < 16) ? Alo : Ahi;
                    int c2 = ck & 15;
                    aaddr = base + (m * 16 + ((c2 & 8) | ((c2 & 7) ^ (m & 7)))) * 16u;
                }
                ldm4(aaddr, a[mt][0], a[mt][1], a[mt][2], a[mt][3]);
            }
#pragma unroll
            for (int np = 0; np < 4; np++) {
                int n   = wn * 64 + np * 16 + (L & 7) + ((L >> 4) << 3);
                int ckb = ks * 2 + ((L >> 3) & 1);
                unsigned b0, b1, b2, b3;
                ldm4(Bb + (n * 4 + (ckb ^ ((n >> 1) & 3))) * 16u, b0, b1, b2, b3);
#pragma unroll
                for (int mt = 0; mt < 2; mt++) {
                    mma_bf16(acc[mt][np * 2 + 0], a[mt][0], a[mt][1], a[mt][2], a[mt][3], b0, b1);
                    mma_bf16(acc[mt][np * 2 + 1], a[mt][0], a[mt][1], a[mt][2], a[mt][3], b2, b3);
                }
            }
        }
        // mid-loop sync protects W ring reuse; final sync only if TRAIL
        if (kc + 1 < NCH) __syncthreads();
        else if (TRAIL)   __syncthreads();
    }

    const int g = L >> 2, q2 = (L & 3) * 2;
#pragma unroll
    for (int mt = 0; mt < 2; mt++) {
#pragma unroll
        for (int nt = 0; nt < 8; nt++) {
            int ng = wn * 64 + nt * 8 + q2;
            float b0 = __ldg(&bias[n0 + ng]), b1 = __ldg(&bias[n0 + ng + 1]);
            int c = ng >> 3;
#pragma unroll
            for (int h = 0; h < 2; h++) {
                int m = wm * 32 + mt * 16 + g + 8 * h;
                float v0 = acc[mt][nt][2 * h + 0] + b0;
                float v1 = acc[mt][nt][2 * h + 1] + b1;
                if (relu) { v0 = fmaxf(v0, 0.0f); v1 = fmaxf(v1, 0.0f); }
                int sw = (c & 8) | ((c & 7) ^ (m & 7));
                *reinterpret_cast<unsigned*>(Ob + (m * 16 + sw) * 16 + (ng & 7) * 2)
                    = pack_bf16(v0, v1);
            }
        }
    }
}

// ---------------------------------------------------------------------------
// Megakernel (256 threads, 128 rows/block, 2 CTAs/SM)
// ---------------------------------------------------------------------------
__global__ __launch_bounds__(256, 2)
void mega_kernel(const float* __restrict__ action,
                 const float* __restrict__ be1, const float* __restrict__ be2,
                 const float* __restrict__ be3, const float* __restrict__ E,
                 const float* __restrict__ bd1, const float* __restrict__ bd2,
                 const float* __restrict__ bh, float* __restrict__ out) {
    extern __shared__ char sm[];
    const int tid = threadIdx.x;
    const int w = tid >> 5, L = tid & 31;
    const int wm = w & 3, wn = w >> 2;
    const int r0 = blockIdx.x * 128;

    char* B0p = sm + B0_OFF;
    char* B1p = sm + B1_OFF;
    char* B2p = sm + B2_OFF;
    unsigned b0a = su(B0p), b1a = su(B1p), b2a = su(B2p);
    unsigned wb  = su(sm + WB_OFF);
    float* esq_s = (float*)(sm + WB_OFF);
    float* red_v = (float*)(sm + WB_OFF + 8192);
    int*   red_i = (int*)  (sm + WB_OFF + 9216);
    int*   bidx  = (int*)  (sm + WB_OFF + 10240);

    // ---- Stage 1: pack action into B0 (ACH=8, K padded to 64); h1 -> B1|B2 ----
    {
        char* sActB = B0p;
        {
            int m = tid >> 1, hf = tid & 1;
            const float* ap = action + (size_t)(r0 + m) * AA + hf * 8;
            float4 f0 = __ldg((const float4*)ap);
            float4 f1 = __ldg((const float4*)(ap + 4));
            uint4 pk;
            pk.x = pack_bf16(f0.x, f0.y); pk.y = pack_bf16(f0.z, f0.w);
            pk.z = pack_bf16(f1.x, f1.y); pk.w = pack_bf16(f1.z, f1.w);
            *reinterpret_cast<uint4*>(sActB + (m * 8 + (hf ^ (m & 7))) * 16) = pk;
        }
        uint4 z = make_uint4(0, 0, 0, 0);
#pragma unroll
        for (int t = 0; t < 3; t++) {
            int idx = tid + t * 256;
            int m = idx / 6, c = 2 + idx % 6;
            *reinterpret_cast<uint4*>(sActB + (m * 8 + (c ^ (m & 7))) * 16) = z;
        }
        __syncthreads();
        gemm_stage<64, 0, false>(b0a, 0, g_We1b,            be1, 0,   B1p, true, wb);
        gemm_stage<64, 0, false>(b0a, 0, g_We1b + 128 * 64, be1, 128, B2p, true, wb);
    }
    // no caller sync: S2c1's chunk-0 opening sync orders stragglers

    // ---- Stage 2: h2 = relu(h1 @ We2^T + be2): A=(B1,B2) -> out B0 | B1 ----
    gemm_stage<256, 2, false>(b1a, b2a, g_We2b,             be2, 0,   B0p, true, wb);
    gemm_stage<256, 2, true >(b1a, b2a, g_We2b + 128 * 256, be2, 128, B1p, true, wb);  // out aliases A
    __syncthreads();

    // ---- Stage 3: enc = h2 @ We3^T + be3: A=(B0,B1) -> out B2 ----
    // TRAIL: dist immediately cp.asyncs E into B0 (this stage's A) — must order.
    gemm_stage<256, 2, true>(b0a, b1a, g_We3b, be3, 0, B2p, false, wb);

    // ---- Stage 4: dist + argmin over 2048 codes; enc=B2, E tiles in B0/B1 ----
    {
        unsigned eaddr = b2a;

#pragma unroll
        for (int t = 0; t < 2; t++) {
            int idx = tid + t * 256;
            cp16(su(esq_s) + idx * 16u, g_esq + idx * 4);
        }
#pragma unroll
        for (int t = 0; t < 8; t++) {
            int idx = tid + t * 256;
            int n = idx >> 4, c = idx & 15;
            int sw = (c & 8) | ((c & 7) ^ (n & 7));
            cp16(b0a + (n * 16 + sw) * 16u, (const char*)g_Eb + (size_t)n * 256 + c * 16);
        }
        cpcommit();

        float bestv[4];
        int   besti[4];
#pragma unroll
        for (int i = 0; i < 4; i++) { bestv[i] = FLT_MAX; besti[i] = 0; }

        const float2* esq2 = (const float2*)esq_s;

        for (int t0 = 0; t0 < 16; t0++) {
            if (t0 + 1 < 16) {
                unsigned bb = (t0 & 1) ? b0a : b1a;
                const char* Eg = (const char*)g_Eb + (size_t)(t0 + 1) * 32768;
#pragma unroll
                for (int t = 0; t < 8; t++) {
                    int idx = tid + t * 256;
                    int n = idx >> 4, c = idx & 15;
                    int sw = (c & 8) | ((c & 7) ^ (n & 7));
                    cp16(bb + (n * 16 + sw) * 16u, Eg + (size_t)n * 256 + c * 16);
                }
                cpcommit();
                cpwait<1>();
            } else {
                cpwait<0>();
            }
            __syncthreads();

            unsigned Bb = (t0 & 1) ? b1a : b0a;
            float acc[2][8][4];
#pragma unroll
            for (int a = 0; a < 2; a++)
#pragma unroll
                for (int b = 0; b < 8; b++)
#pragma unroll
                    for (int c = 0; c < 4; c++) acc[a][b][c] = 0.0f;

#pragma unroll
            for (int ks = 0; ks < 8; ks++) {
                unsigned a[2][4];
#pragma unroll
                for (int mt = 0; mt < 2; mt++) {
                    int m  = wm * 32 + mt * 16 + (L & 15);
                    int ck = ks * 2 + (L >> 4);
                    int sw = (ck & 8) | ((ck & 7) ^ (m & 7));
                    ldm4(eaddr + (m * 16 + sw) * 16u, a[mt][0], a[mt][1], a[mt][2], a[mt][3]);
                }
#pragma unroll
                for (int np = 0; np < 4; np++) {
                    int n   = wn * 64 + np * 16 + (L & 7) + ((L >> 4) << 3);
                    int ckb = ks * 2 + ((L >> 3) & 1);
                    int sw  = (ckb & 8) | ((ckb & 7) ^ (n & 7));
                    unsigned b0, b1, b2, b3;
                    ldm4(Bb + (n * 16 + sw) * 16u, b0, b1, b2, b3);
#pragma unroll
                    for (int mt = 0; mt < 2; mt++) {
                        mma_bf16(acc[mt][np * 2 + 0], a[mt][0], a[mt][1], a[mt][2], a[mt][3], b0, b1);
                        mma_bf16(acc[mt][np * 2 + 1], a[mt][0], a[mt][1], a[mt][2], a[mt][3], b2, b3);
                    }
                }
            }

            const int q2 = (L & 3) * 2;
#pragma unroll
            for (int nt = 0; nt < 8; nt++) {
                int n = t0 * 128 + wn * 64 + nt * 8 + q2;
                float2 es = esq2[n >> 1];
#pragma unroll
                for (int mt = 0; mt < 2; mt++) {
#pragma unroll
                    for (int h = 0; h < 2; h++) {
                        int r = mt * 2 + h;
                        float v0 = fmaf(-2.0f, acc[mt][nt][2 * h + 0], es.x);
                        float v1 = fmaf(-2.0f, acc[mt][nt][2 * h + 1], es.y);
                        if (v0 < bestv[r]) { bestv[r] = v0; besti[r] = n; }
                        if (v1 < bestv[r]) { bestv[r] = v1; besti[r] = n + 1; }
                    }
                }
            }
            __syncthreads();
        }

#pragma unroll
        for (int r = 0; r < 4; r++) {
            float v = bestv[r];
            int   ii = besti[r];
#pragma unroll
            for (int o = 1; o <= 2; o <<= 1) {
                float v2 = __shfl_xor_sync(0xffffffffu, v, o);
                int   i2 = __shfl_xor_sync(0xffffffffu, ii, o);
                if (v2 < v || (v2 == v && i2 < ii)) { v = v2; ii = i2; }
            }
            bestv[r] = v; besti[r] = ii;
        }
        if ((L & 3) == 0) {
            int g = L >> 2;
#pragma unroll
            for (int r = 0; r < 4; r++) {
                int mt = r >> 1, h = r & 1;
                int row = wm * 32 + mt * 16 + g + 8 * h;
                red_v[row * 2 + wn] = bestv[r];
                red_i[row * 2 + wn] = besti[r];
            }
        }
        __syncthreads();
        if (tid < 128) {
            float v0 = red_v[tid * 2], v1 = red_v[tid * 2 + 1];
            int   i0 = red_i[tid * 2], i1 = red_i[tid * 2 + 1];
            bidx[tid] = (v1 < v0 || (v1 == v0 && i1 < i0)) ? i1 : i0;
        }
        __syncthreads();
    }

    // ---- Stage 5: gather q = E[idx] -> B0 (swizzled), vq loss (enc in B2) ----
    {
        int m = tid >> 1, hf = tid & 1;
        int code = bidx[m];
        const float4* Ep = reinterpret_cast<const float4*>(E + ((size_t)code << 7) + hf * 64);
        float s = 0.0f;
#pragma unroll
        for (int j = 0; j < 8; j++) {
            int c = hf * 8 + j;
            float4 q0 = __ldg(&Ep[2 * j]);
            float4 q1 = __ldg(&Ep[2 * j + 1]);
            int sw = (c & 8) | ((c & 7) ^ (m & 7));
            uint4 ev = *reinterpret_cast<uint4*>(B2p + (m * 16 + sw) * 16);
            const __nv_bfloat162* eh = reinterpret_cast<const __nv_bfloat162*>(&ev);
            float2 e0 = __bfloat1622float2(eh[0]);
            float2 e1 = __bfloat1622float2(eh[1]);
            float2 e2 = __bfloat1622float2(eh[2]);
            float2 e3 = __bfloat1622float2(eh[3]);
            float d;
            d = e0.x - q0.x; s += d * d;  d = e0.y - q0.y; s += d * d;
            d = e1.x - q0.z; s += d * d;  d = e1.y - q0.w; s += d * d;
            d = e2.x - q1.x; s += d * d;  d = e2.y - q1.y; s += d * d;
            d = e3.x - q1.z; s += d * d;  d = e3.y - q1.w; s += d * d;
            uint4 pk;
            pk.x = pack_bf16(q0.x, q0.y); pk.y = pack_bf16(q0.z, q0.w);
            pk.z = pack_bf16(q1.x, q1.y); pk.w = pack_bf16(q1.z, q1.w);
            *reinterpret_cast<uint4*>(B0p + (m * 16 + sw) * 16) = pk;
        }
        block_reduce_add_to(s, &g_sums[0]);
    }
    __syncthreads();

    // ---- Stage 6: d1 = relu(q @ Wd1^T + bd1): A=B0 -> out B1 | B2 ----
    gemm_stage<128, 1, false>(b0a, 0, g_Wd1b,             bd1, 0,   B1p, true, wb);
    gemm_stage<128, 1, false>(b0a, 0, g_Wd1b + 128 * 128, bd1, 128, B2p, true, wb);
    // no caller sync: S7c1's opening sync orders stragglers

    // ---- Stage 7: d2 = relu(d1 @ Wd2^T + bd2): A=(B1,B2) -> out B0 | B1 ----
    gemm_stage<256, 2, false>(b1a, b2a, g_Wd2b,             bd2, 0,   B0p, true, wb);
    gemm_stage<256, 2, true >(b1a, b2a, g_Wd2b + 128 * 256, bd2, 128, B1p, true, wb);  // alias

    // ---- Stage 8: head = tanh(d2 @ Wh^T + bh), recons loss; A=(B0,B1) ----
    {
        unsigned whaddr = wb;   // 16 x 256 bf16 swizzled (8KB)
#pragma unroll
        for (int i = 0; i < 2; i++) {
            int idx = tid * 2 + i;
            int n = idx >> 5, c = idx & 31;
            int sw = (c & 24) | ((c & 7) ^ (n & 7));
            cp16(whaddr + (n * 32 + sw) * 16u, g_Whb + (size_t)n * HH + c * 8);
        }
        cpcommit(); cpwait<0>();
        __syncthreads();

        float acc[2][4];
#pragma unroll
        for (int a = 0; a < 2; a++)
#pragma unroll
            for (int c = 0; c < 4; c++) acc[a][c] = 0.0f;

#pragma unroll
        for (int ks = 0; ks < 16; ks++) {
            int m  = w * 16 + (L & 15);
            int ck = ks * 2 + (L >> 4);
            unsigned base = (ck < 16) ? b0a : b1a;
            int c2 = ck & 15;
            int sw = (c2 & 8) | ((c2 & 7) ^ (m & 7));
            unsigned a0, a1, a2, a3;
            ldm4(base + (m * 16 + sw) * 16u, a0, a1, a2, a3);
            int n   = (L & 7) + ((L >> 4) << 3);
            int ckb = ks * 2 + ((L >> 3) & 1);
            int swb = (ckb & 24) | ((ckb & 7) ^ (n & 7));
            unsigned b0, b1, b2, b3;
            ldm4(whaddr + (n * 32 + swb) * 16u, b0, b1, b2, b3);
            mma_bf16(acc[0], a0, a1, a2, a3, b0, b1);
            mma_bf16(acc[1], a0, a1, a2, a3, b2, b3);
        }

        const int g = L >> 2, q2 = (L & 3) * 2;
        float s = 0.0f;
#pragma unroll
        for (int nt = 0; nt < 2; nt++) {
            int n = nt * 8 + q2;
            float b0 = __ldg(&bh[n]), b1 = __ldg(&bh[n + 1]);
#pragma unroll
            for (int h = 0; h < 2; h++) {
                int m = w * 16 + g + 8 * h;
                const float* ar = action + (size_t)(r0 + m) * AA + n;
                float t0 = tanhf(acc[nt][2 * h + 0] + b0) - __ldg(&ar[0]);
                float t1 = tanhf(acc[nt][2 * h + 1] + b1) - __ldg(&ar[1]);
                s += t0 * t0 + t1 * t1;
            }
        }
        block_reduce_add_to(s, &g_sums[1]);
    }

    // ---- fused finalize ----
    if (tid == 0) {
        __threadfence();
        unsigned t = atomicAdd(&g_ticket, 1u);
        if (t == gridDim.x - 1) {
            double vq  = g_sums[0] / ((double)BB * (double)DD);
            double rec = g_sums[1] / ((double)BB * (double)AA);
            out[0] = (float)(rec + 1.25 * vq);
        }
    }
}

// ---------------------------------------------------------------------------
extern "C" void kernel_launch(void* const* d_in, const int* in_sizes, int n_in,
                              void* d_out, int out_size) {
    const float* action = (const float*)d_in[0];
    const float* We1    = (const float*)d_in[1];
    const float* be1    = (const float*)d_in[2];
    const float* We2    = (const float*)d_in[3];
    const float* be2    = (const float*)d_in[4];
    const float* We3    = (const float*)d_in[5];
    const float* be3    = (const float*)d_in[6];
    const float* E      = (const float*)d_in[7];
    const float* Wd1    = (const float*)d_in[8];
    const float* bd1    = (const float*)d_in[9];
    const float* Wd2    = (const float*)d_in[10];
    const float* bd2    = (const float*)d_in[11];
    const float* Wh     = (const float*)d_in[12];
    const float* bh     = (const float*)d_in[13];
    float* out = (float*)d_out;

    cudaFuncSetAttribute((const void*)mega_kernel,
                         cudaFuncAttributeMaxDynamicSharedMemorySize, SMEM_TOTAL);

    prep_kernel<<<464, 256>>>((const float4*)We1, (const float4*)We2,
                              (const float4*)We3, (const float4*)Wd1,
                              (const float4*)Wd2, (const float4*)Wh,
                              (const float4*)E, E);
    mega_kernel<<<BB / 128, 256, SMEM_TOTAL>>>(action, be1, be2, be3, E,
                                               bd1, bd2, bh, out);
}